// round 5
// baseline (speedup 1.0000x reference)
#include <cuda_runtime.h>
#include <cstdint>

#define BATCH 8
#define CH    16
#define HH    256
#define WW    256
#define HW    (HH*WW)
#define NPTS  (BATCH*HH*WW)            // 524288 grid points
#define SCRATCH_F4 (NPTS*4)            // [b][i][j][c]: 2,097,152 float4 = 33.5 MB

// Scratch accumulator, channels innermost: scratch[b][i][j][c].
__device__ float4 g_scratch4[SCRATCH_F4];

__device__ __forceinline__ float getc(const float4& v, int p) {
    return p == 0 ? v.x : p == 1 ? v.y : p == 2 ? v.z : v.w;
}

// ---------------------------------------------------------------------------
// Kernel 1: zero the scratch accumulator. 2 float4 stores per thread (ILP).
// ---------------------------------------------------------------------------
__global__ void __launch_bounds__(256) zero_kernel() {
    int t = blockIdx.x * blockDim.x + threadIdx.x;   // 0 .. SCRATCH_F4/2-1
    const float4 z = make_float4(0.f, 0.f, 0.f, 0.f);
    g_scratch4[2 * t + 0] = z;
    g_scratch4[2 * t + 1] = z;
}

// ---------------------------------------------------------------------------
// Kernel 2: scatter. 4 consecutive (same-b) grid points per thread.
//   Per channel, the 4 points' x values are one contiguous float4 (LDG.128),
//   minimizing LSU ops (scatter is LSU-issue bound: 8.39M RED + 2.1M LDG).
//   Per point: 4 bilinear taps, each = 4x atomicAdd(float4) into scratch.
// ---------------------------------------------------------------------------
__global__ void __launch_bounds__(128) scatter_kernel(
    const float4* __restrict__ x4, const float4* __restrict__ grid4)
{
    int t = blockIdx.x * blockDim.x + threadIdx.x;   // 0 .. NPTS/4-1
    int b   = t >> 14;                               // (4t) >> 16
    int hw4 = t & 0x3FFF;                            // hw/4

    // grid: [b][h][w][2] float -> 4 points = 2 float4
    float4 ga = grid4[2 * t + 0];    // p0:(x,y) p1:(x,y)
    float4 gb = grid4[2 * t + 1];    // p2:(x,y) p3:(x,y)
    float gx[4] = {ga.x, ga.z, gb.x, gb.z};
    float gy[4] = {ga.y, ga.w, gb.y, gb.w};

    // x: [b][c][h][w]; one float4 per channel covers the 4 points.
    const float4* xp = x4 + ((size_t)b * (CH * HW) >> 2) + hw4;
    float4 xv[CH];
#pragma unroll
    for (int c = 0; c < CH; c++) xv[c] = xp[(size_t)c * (HW / 4)];

#pragma unroll
    for (int p = 0; p < 4; p++) {
        float ci = fminf(fmaxf((gx[p] + 1.0f) * 0.5f * 256.0f + 1.0f, 0.0f), 257.0f);
        float cj = fminf(fmaxf((gy[p] + 1.0f) * 0.5f * 256.0f + 1.0f, 0.0f), 257.0f);

        float fi0 = floorf(ci), fj0 = floorf(cj);
        int   i0 = (int)fi0,    j0 = (int)fj0;
        float fi = ci - fi0,    fj = cj - fj0;       // in [0,1)

        float wi[2] = {1.0f - fi, fi};
        float wj[2] = {1.0f - fj, fj};

#pragma unroll
        for (int di = 0; di < 2; di++) {
            int oi = i0 + di - 1;
            if ((unsigned)oi >= 256u) continue;
#pragma unroll
            for (int dj = 0; dj < 2; dj++) {
                int oj = j0 + dj - 1;
                if ((unsigned)oj >= 256u) continue;
                float wt = wi[di] * wj[dj];
                float4* dst = g_scratch4 + ((((size_t)b << 8 | oi) << 8 | oj) << 2);
#pragma unroll
                for (int k = 0; k < 4; k++) {
                    atomicAdd(dst + k,
                              make_float4(getc(xv[4*k + 0], p) * wt,
                                          getc(xv[4*k + 1], p) * wt,
                                          getc(xv[4*k + 2], p) * wt,
                                          getc(xv[4*k + 3], p) * wt));
                }
            }
        }
    }
}

// ---------------------------------------------------------------------------
// Kernel 3: transpose scratch [b][i][j][c] -> out [b][c][i][j].
// One block per (b,i) row: load 256*16 floats coalesced (float4), stage in
// smem with stride-17 padding, write 16 coalesced 1KB channel segments.
// NO zero-restore here (R3 showed that fusion costs ~+20us).
// ---------------------------------------------------------------------------
__global__ void __launch_bounds__(256) transpose_kernel(float* __restrict__ out) {
    __shared__ float s[256 * 17];
    int bi  = blockIdx.x;            // b*256 + i
    int tid = threadIdx.x;           // 0..255

    const float4* src = g_scratch4 + (size_t)bi * (256 * 4);   // 1024 float4 per row
#pragma unroll
    for (int it = 0; it < 4; it++) {
        int e = it * 256 + tid;      // float4 index within row
        float4 v = src[e];
        int j  = e >> 2;             // pixel column 0..255
        int cq = (e & 3) * 4;        // channel quad base 0/4/8/12
        float* sp = s + j * 17 + cq;
        sp[0] = v.x; sp[1] = v.y; sp[2] = v.z; sp[3] = v.w;
    }
    __syncthreads();

    int b = bi >> 8, i = bi & 255;
    float* op = out + ((size_t)b * CH * HH + i) * WW + tid;    // out[b][c][i][tid]
#pragma unroll
    for (int c = 0; c < CH; c++)
        op[(size_t)c * HW] = s[tid * 17 + c];                  // conflict-free
}

// ---------------------------------------------------------------------------
extern "C" void kernel_launch(void* const* d_in, const int* in_sizes, int n_in,
                              void* d_out, int out_size)
{
    const float* x    = (const float*)d_in[0];
    const float* grid = (const float*)d_in[1];
    if (in_sizes[0] != BATCH * CH * HW) {     // pick by size, defensively
        const float* t = x; x = grid; grid = t;
    }

    zero_kernel<<<(SCRATCH_F4 / 2) / 256, 256>>>();
    scatter_kernel<<<(NPTS / 4) / 128, 128>>>((const float4*)x, (const float4*)grid);
    transpose_kernel<<<BATCH * HH, 256>>>((float*)d_out);
}

// round 6
// speedup vs baseline: 1.4911x; 1.4911x over previous
#include <cuda_runtime.h>
#include <cuda_fp16.h>
#include <cstdint>

#define BATCH 8
#define CH    16
#define HH    256
#define WW    256
#define HW    (HH*WW)
#define NPTS  (BATCH*HH*WW)              // 524288 grid points / output cells
#define SCRATCH_U4 (NPTS*2)              // cell = 16 half = 32B = 2 uint4; 16.7 MB

// f16 scratch accumulator, channels innermost: [b][i][j][c(half)].
__device__ uint4 g_scratchv[SCRATCH_U4];

__device__ __forceinline__ float getc(const float4& v, int p) {
    return p == 0 ? v.x : p == 1 ? v.y : p == 2 ? v.z : v.w;
}

// ---------------------------------------------------------------------------
// Kernel 1: zero the f16 scratch (coalesced, 1 uint4 per thread).
// ---------------------------------------------------------------------------
__global__ void __launch_bounds__(256) zero_kernel() {
    int idx = blockIdx.x * blockDim.x + threadIdx.x;
    g_scratchv[idx] = make_uint4(0u, 0u, 0u, 0u);
}

// ---------------------------------------------------------------------------
// Kernel 2: scatter, 4 consecutive (same-b) points per thread.
// x loaded as float4 per channel (covers the 4 points), converted ONCE to
// half2 pairs over channels; per tap: 8 HMUL2 + 2x red.v4.f16x2 (16B each).
// ---------------------------------------------------------------------------
__global__ void __launch_bounds__(128) scatter_kernel(
    const float4* __restrict__ x4, const float4* __restrict__ grid4)
{
    int t = blockIdx.x * blockDim.x + threadIdx.x;   // 0 .. NPTS/4-1
    int b   = t >> 14;
    int hw4 = t & 0x3FFF;

    float4 ga = grid4[2 * t + 0];    // p0:(x,y) p1:(x,y)
    float4 gb = grid4[2 * t + 1];    // p2:(x,y) p3:(x,y)
    float gx[4] = {ga.x, ga.z, gb.x, gb.z};
    float gy[4] = {ga.y, ga.w, gb.y, gb.w};

    const float4* xp = x4 + ((size_t)b * (CH * HW) >> 2) + hw4;
    float4 xv[CH];
#pragma unroll
    for (int c = 0; c < CH; c++) xv[c] = xp[(size_t)c * (HW / 4)];

    // xh[p][cp] = half2(x[2cp], x[2cp+1]) for point p  (32 regs)
    __half2 xh[4][8];
#pragma unroll
    for (int cp = 0; cp < 8; cp++)
#pragma unroll
        for (int p = 0; p < 4; p++)
            xh[p][cp] = __floats2half2_rn(getc(xv[2*cp],   p),
                                          getc(xv[2*cp+1], p));

    char* sbase = reinterpret_cast<char*>(g_scratchv);

#pragma unroll
    for (int p = 0; p < 4; p++) {
        float ci = fminf(fmaxf((gx[p] + 1.0f) * 0.5f * 256.0f + 1.0f, 0.0f), 257.0f);
        float cj = fminf(fmaxf((gy[p] + 1.0f) * 0.5f * 256.0f + 1.0f, 0.0f), 257.0f);

        float fi0 = floorf(ci), fj0 = floorf(cj);
        int   i0 = (int)fi0,    j0 = (int)fj0;
        float fi = ci - fi0,    fj = cj - fj0;       // in [0,1)

        float wi[2] = {1.0f - fi, fi};
        float wj[2] = {1.0f - fj, fj};

#pragma unroll
        for (int di = 0; di < 2; di++) {
            int oi = i0 + di - 1;
            if ((unsigned)oi >= 256u) continue;
#pragma unroll
            for (int dj = 0; dj < 2; dj++) {
                int oj = j0 + dj - 1;
                if ((unsigned)oj >= 256u) continue;
                __half2 wt2 = __float2half2_rn(wi[di] * wj[dj]);
                // cell byte offset: ((b,oi,oj)) * 32B
                size_t cell = ((((size_t)b << 8 | oi) << 8 | oj) << 5);
#pragma unroll
                for (int k = 0; k < 2; k++) {
                    __half2 h0 = __hmul2(xh[p][4*k + 0], wt2);
                    __half2 h1 = __hmul2(xh[p][4*k + 1], wt2);
                    __half2 h2 = __hmul2(xh[p][4*k + 2], wt2);
                    __half2 h3 = __hmul2(xh[p][4*k + 3], wt2);
                    asm volatile(
                        "red.global.add.noftz.v4.f16x2 [%0], {%1, %2, %3, %4};"
                        :: "l"(sbase + cell + 16*k),
                           "r"(*(unsigned*)&h0), "r"(*(unsigned*)&h1),
                           "r"(*(unsigned*)&h2), "r"(*(unsigned*)&h3)
                        : "memory");
                }
            }
        }
    }
}

// ---------------------------------------------------------------------------
// Kernel 3: transpose f16 scratch [b][i][j][c] -> f32 out [b][c][i][j].
// No smem: thread owns 4 consecutive cells (128B contiguous), assembles
// per-channel float4 in registers, 16 coalesced STG.128.
// ---------------------------------------------------------------------------
__global__ void __launch_bounds__(256) transpose_kernel(float* __restrict__ out) {
    int tid = threadIdx.x;
    int r   = tid >> 6;                      // row within block (0..3)
    int q   = tid & 63;                      // j-quad (0..63), j0 = 4q
    int bi  = blockIdx.x * 4 + r;            // b*256 + i
    int b = bi >> 8, i = bi & 255;

    // 4 cells = 8 uint4, contiguous.
    const uint4* src = g_scratchv + (size_t)bi * 512 + q * 8;
    uint4 cv[8];
#pragma unroll
    for (int m = 0; m < 8; m++) cv[m] = src[m];

    float* op = out + ((size_t)b * CH * HH + i) * WW + 4 * q;
#pragma unroll
    for (int c = 0; c < CH; c++) {
        float v[4];
#pragma unroll
        for (int m = 0; m < 4; m++) {
            uint4 u = cv[2*m + (c >> 3)];
            int sel = (c >> 1) & 3;
            unsigned wbits = sel == 0 ? u.x : sel == 1 ? u.y : sel == 2 ? u.z : u.w;
            __half2 h = *reinterpret_cast<__half2*>(&wbits);
            float2 f = __half22float2(h);
            v[m] = (c & 1) ? f.y : f.x;
        }
        *reinterpret_cast<float4*>(op + (size_t)c * HW) =
            make_float4(v[0], v[1], v[2], v[3]);
    }
}

// ---------------------------------------------------------------------------
extern "C" void kernel_launch(void* const* d_in, const int* in_sizes, int n_in,
                              void* d_out, int out_size)
{
    const float* x    = (const float*)d_in[0];
    const float* grid = (const float*)d_in[1];
    if (in_sizes[0] != BATCH * CH * HW) {     // pick by size, defensively
        const float* t = x; x = grid; grid = t;
    }

    zero_kernel<<<SCRATCH_U4 / 256, 256>>>();
    scatter_kernel<<<(NPTS / 4) / 128, 128>>>((const float4*)x, (const float4*)grid);
    transpose_kernel<<<(BATCH * HH) / 4, 256>>>((float*)d_out);
}

// round 11
// speedup vs baseline: 1.6994x; 1.1397x over previous
#include <cuda_runtime.h>
#include <cuda_fp16.h>
#include <cstdint>

#define BATCH 8
#define CH    16
#define HH    256
#define WW    256
#define HW    (HH*WW)
#define NPTS  (BATCH*HH*WW)              // 524288 grid points / output cells
#define SCRATCH_U4 (NPTS*2)              // cell = 16 half = 32B = 2 uint4; 16.7 MB

// f16 scratch accumulator, channels innermost: [b][i][j][c(half)].
__device__ uint4 g_scratchv[SCRATCH_U4];

// ---------------------------------------------------------------------------
// Kernel 1: zero the f16 scratch. 2 coalesced uint4 stores per thread.
// ---------------------------------------------------------------------------
__global__ void __launch_bounds__(256) zero_kernel() {
    int idx = blockIdx.x * blockDim.x + threadIdx.x;   // 0 .. SCRATCH_U4/2-1
    const uint4 z = make_uint4(0u, 0u, 0u, 0u);
    g_scratchv[idx] = z;
    g_scratchv[idx + SCRATCH_U4 / 2] = z;
}

// ---------------------------------------------------------------------------
// Kernel 2: scatter, 2 consecutive (same-b) points per thread, 256 thr/block
// (8192 warps total -> ~2 waves/SM, keeps the L2 atomic path saturated).
// x loaded as float2 per channel, converted once to half2 per point;
// per tap: 1 FMUL + 8 HMUL2 + 2x red.global.add.noftz.v4.f16x2 (16B each).
// ---------------------------------------------------------------------------
__global__ void __launch_bounds__(256) scatter_kernel(
    const float2* __restrict__ x2, const float4* __restrict__ grid4)
{
    int t = blockIdx.x * blockDim.x + threadIdx.x;   // 0 .. NPTS/2-1
    int b   = t >> 15;                               // (2t) >> 16
    int hw2 = t & 0x7FFF;                            // hw/2

    // grid: [b][h][w][2] -> 2 points = 1 float4: p0:(x,y) p1:(x,y)
    float4 g = grid4[t];
    float gx[2] = {g.x, g.z};
    float gy[2] = {g.y, g.w};

    // x: [b][c][h][w]; one float2 per channel covers both points.
    const float2* xp = x2 + ((size_t)b * (CH * HW) >> 1) + hw2;
    float2 xv[CH];
#pragma unroll
    for (int c = 0; c < CH; c++) xv[c] = xp[(size_t)c * (HW / 2)];

    // xh[p][cp] = half2(x[2cp], x[2cp+1]) for point p  (16 regs)
    __half2 xh[2][8];
#pragma unroll
    for (int cp = 0; cp < 8; cp++) {
        xh[0][cp] = __floats2half2_rn(xv[2*cp].x, xv[2*cp+1].x);
        xh[1][cp] = __floats2half2_rn(xv[2*cp].y, xv[2*cp+1].y);
    }

    char* sbase = reinterpret_cast<char*>(g_scratchv);

#pragma unroll
    for (int p = 0; p < 2; p++) {
        float ci = fminf(fmaxf((gx[p] + 1.0f) * 0.5f * 256.0f + 1.0f, 0.0f), 257.0f);
        float cj = fminf(fmaxf((gy[p] + 1.0f) * 0.5f * 256.0f + 1.0f, 0.0f), 257.0f);

        float fi0 = floorf(ci), fj0 = floorf(cj);
        int   i0 = (int)fi0,    j0 = (int)fj0;
        float fi = ci - fi0,    fj = cj - fj0;       // in [0,1)

        float wi[2] = {1.0f - fi, fi};
        float wj[2] = {1.0f - fj, fj};

#pragma unroll
        for (int di = 0; di < 2; di++) {
            int oi = i0 + di - 1;
            if ((unsigned)oi >= 256u) continue;
#pragma unroll
            for (int dj = 0; dj < 2; dj++) {
                int oj = j0 + dj - 1;
                if ((unsigned)oj >= 256u) continue;
                __half2 wt2 = __float2half2_rn(wi[di] * wj[dj]);
                size_t cell = ((((size_t)b << 8 | oi) << 8 | oj) << 5);  // *32B
#pragma unroll
                for (int k = 0; k < 2; k++) {
                    __half2 h0 = __hmul2(xh[p][4*k + 0], wt2);
                    __half2 h1 = __hmul2(xh[p][4*k + 1], wt2);
                    __half2 h2 = __hmul2(xh[p][4*k + 2], wt2);
                    __half2 h3 = __hmul2(xh[p][4*k + 3], wt2);
                    asm volatile(
                        "red.global.add.noftz.v4.f16x2 [%0], {%1, %2, %3, %4};"
                        :: "l"(sbase + cell + 16*k),
                           "r"(*(unsigned*)&h0), "r"(*(unsigned*)&h1),
                           "r"(*(unsigned*)&h2), "r"(*(unsigned*)&h3)
                        : "memory");
                }
            }
        }
    }
}

// ---------------------------------------------------------------------------
// Kernel 3: transpose f16 scratch [b][i][j][c] -> f32 out [b][c][i][j].
// No smem: thread owns 4 consecutive cells (128B contiguous), assembles
// per-channel float4 in registers, 16 coalesced STG.128.
// ---------------------------------------------------------------------------
__global__ void __launch_bounds__(256) transpose_kernel(float* __restrict__ out) {
    int tid = threadIdx.x;
    int r   = tid >> 6;                      // row within block (0..3)
    int q   = tid & 63;                      // j-quad (0..63), j0 = 4q
    int bi  = blockIdx.x * 4 + r;            // b*256 + i
    int b = bi >> 8, i = bi & 255;

    // 4 cells = 8 uint4, contiguous.
    const uint4* src = g_scratchv + (size_t)bi * 512 + q * 8;
    uint4 cv[8];
#pragma unroll
    for (int m = 0; m < 8; m++) cv[m] = src[m];

    float* op = out + ((size_t)b * CH * HH + i) * WW + 4 * q;
#pragma unroll
    for (int c = 0; c < CH; c++) {
        float v[4];
#pragma unroll
        for (int m = 0; m < 4; m++) {
            uint4 u = cv[2*m + (c >> 3)];
            int sel = (c >> 1) & 3;
            unsigned wbits = sel == 0 ? u.x : sel == 1 ? u.y : sel == 2 ? u.z : u.w;
            __half2 h = *reinterpret_cast<__half2*>(&wbits);
            float2 f = __half22float2(h);
            v[m] = (c & 1) ? f.y : f.x;
        }
        *reinterpret_cast<float4*>(op + (size_t)c * HW) =
            make_float4(v[0], v[1], v[2], v[3]);
    }
}

// ---------------------------------------------------------------------------
extern "C" void kernel_launch(void* const* d_in, const int* in_sizes, int n_in,
                              void* d_out, int out_size)
{
    const float* x    = (const float*)d_in[0];
    const float* grid = (const float*)d_in[1];
    if (in_sizes[0] != BATCH * CH * HW) {     // pick by size, defensively
        const float* t = x; x = grid; grid = t;
    }

    zero_kernel<<<(SCRATCH_U4 / 2) / 256, 256>>>();
    scatter_kernel<<<(NPTS / 2) / 256, 256>>>((const float2*)x, (const float4*)grid);
    transpose_kernel<<<(BATCH * HH) / 4, 256>>>((float*)d_out);
}

// round 12
// speedup vs baseline: 1.7183x; 1.0111x over previous
#include <cuda_runtime.h>
#include <cuda_fp16.h>
#include <cstdint>

#define BATCH 8
#define CH    16
#define HH    256
#define WW    256
#define HW    (HH*WW)
#define NPTS  (BATCH*HH*WW)              // 524288 grid points / output cells
#define SCRATCH_U4 (NPTS*2)              // cell = 16 half = 32B = 2 uint4; 16.7 MB

// f16 scratch accumulator, channels innermost: [b][i][j][c(half)].
__device__ uint4 g_scratchv[SCRATCH_U4];

// ---------------------------------------------------------------------------
// Kernel 1: zero the f16 scratch. Grid-stride, 8 independent coalesced
// STG.128 per thread (MLP=8) — latency/launch bound before, ~L2-write bound now.
// ---------------------------------------------------------------------------
#define ZBLOCKS 512
#define ZTHREADS 256
#define ZITER (SCRATCH_U4 / (ZBLOCKS * ZTHREADS))   // 8
__global__ void __launch_bounds__(ZTHREADS) zero_kernel() {
    int tid = blockIdx.x * ZTHREADS + threadIdx.x;   // 0 .. 131071
    const uint4 z = make_uint4(0u, 0u, 0u, 0u);
#pragma unroll
    for (int i = 0; i < ZITER; i++)
        g_scratchv[tid + i * (ZBLOCKS * ZTHREADS)] = z;
}

// ---------------------------------------------------------------------------
// Kernel 2: scatter, 2 consecutive (same-b) points per thread, 256 thr/block
// (8192 warps total -> 2 waves/SM, keeps the L2 atomic path saturated).
// x loaded as float2 per channel, converted once to half2 per point;
// per tap: 1 FMUL + 8 HMUL2 + 2x red.global.add.noftz.v4.f16x2 (16B each).
// ---------------------------------------------------------------------------
__global__ void __launch_bounds__(256) scatter_kernel(
    const float2* __restrict__ x2, const float4* __restrict__ grid4)
{
    int t = blockIdx.x * blockDim.x + threadIdx.x;   // 0 .. NPTS/2-1
    int b   = t >> 15;                               // (2t) >> 16
    int hw2 = t & 0x7FFF;                            // hw/2

    // grid: [b][h][w][2] -> 2 points = 1 float4: p0:(x,y) p1:(x,y)
    float4 g = grid4[t];
    float gx[2] = {g.x, g.z};
    float gy[2] = {g.y, g.w};

    // x: [b][c][h][w]; one float2 per channel covers both points.
    const float2* xp = x2 + ((size_t)b * (CH * HW) >> 1) + hw2;
    float2 xv[CH];
#pragma unroll
    for (int c = 0; c < CH; c++) xv[c] = xp[(size_t)c * (HW / 2)];

    // xh[p][cp] = half2(x[2cp], x[2cp+1]) for point p  (16 regs)
    __half2 xh[2][8];
#pragma unroll
    for (int cp = 0; cp < 8; cp++) {
        xh[0][cp] = __floats2half2_rn(xv[2*cp].x, xv[2*cp+1].x);
        xh[1][cp] = __floats2half2_rn(xv[2*cp].y, xv[2*cp+1].y);
    }

    char* sbase = reinterpret_cast<char*>(g_scratchv);

#pragma unroll
    for (int p = 0; p < 2; p++) {
        float ci = fminf(fmaxf((gx[p] + 1.0f) * 0.5f * 256.0f + 1.0f, 0.0f), 257.0f);
        float cj = fminf(fmaxf((gy[p] + 1.0f) * 0.5f * 256.0f + 1.0f, 0.0f), 257.0f);

        float fi0 = floorf(ci), fj0 = floorf(cj);
        int   i0 = (int)fi0,    j0 = (int)fj0;
        float fi = ci - fi0,    fj = cj - fj0;       // in [0,1)

        float wi[2] = {1.0f - fi, fi};
        float wj[2] = {1.0f - fj, fj};

#pragma unroll
        for (int di = 0; di < 2; di++) {
            int oi = i0 + di - 1;
            if ((unsigned)oi >= 256u) continue;
#pragma unroll
            for (int dj = 0; dj < 2; dj++) {
                int oj = j0 + dj - 1;
                if ((unsigned)oj >= 256u) continue;
                __half2 wt2 = __float2half2_rn(wi[di] * wj[dj]);
                size_t cell = ((((size_t)b << 8 | oi) << 8 | oj) << 5);  // *32B
#pragma unroll
                for (int k = 0; k < 2; k++) {
                    __half2 h0 = __hmul2(xh[p][4*k + 0], wt2);
                    __half2 h1 = __hmul2(xh[p][4*k + 1], wt2);
                    __half2 h2 = __hmul2(xh[p][4*k + 2], wt2);
                    __half2 h3 = __hmul2(xh[p][4*k + 3], wt2);
                    asm volatile(
                        "red.global.add.noftz.v4.f16x2 [%0], {%1, %2, %3, %4};"
                        :: "l"(sbase + cell + 16*k),
                           "r"(*(unsigned*)&h0), "r"(*(unsigned*)&h1),
                           "r"(*(unsigned*)&h2), "r"(*(unsigned*)&h3)
                        : "memory");
                }
            }
        }
    }
}

// ---------------------------------------------------------------------------
// Kernel 3: transpose f16 scratch [b][i][j][c] -> f32 out [b][c][i][j].
// No smem: thread owns 4 consecutive cells (128B contiguous), assembles
// per-channel float4 in registers, 16 coalesced STG.128.
// ---------------------------------------------------------------------------
__global__ void __launch_bounds__(256) transpose_kernel(float* __restrict__ out) {
    int tid = threadIdx.x;
    int r   = tid >> 6;                      // row within block (0..3)
    int q   = tid & 63;                      // j-quad (0..63), j0 = 4q
    int bi  = blockIdx.x * 4 + r;            // b*256 + i
    int b = bi >> 8, i = bi & 255;

    // 4 cells = 8 uint4, contiguous.
    const uint4* src = g_scratchv + (size_t)bi * 512 + q * 8;
    uint4 cv[8];
#pragma unroll
    for (int m = 0; m < 8; m++) cv[m] = src[m];

    float* op = out + ((size_t)b * CH * HH + i) * WW + 4 * q;
#pragma unroll
    for (int c = 0; c < CH; c++) {
        float v[4];
#pragma unroll
        for (int m = 0; m < 4; m++) {
            uint4 u = cv[2*m + (c >> 3)];
            int sel = (c >> 1) & 3;
            unsigned wbits = sel == 0 ? u.x : sel == 1 ? u.y : sel == 2 ? u.z : u.w;
            __half2 h = *reinterpret_cast<__half2*>(&wbits);
            float2 f = __half22float2(h);
            v[m] = (c & 1) ? f.y : f.x;
        }
        *reinterpret_cast<float4*>(op + (size_t)c * HW) =
            make_float4(v[0], v[1], v[2], v[3]);
    }
}

// ---------------------------------------------------------------------------
extern "C" void kernel_launch(void* const* d_in, const int* in_sizes, int n_in,
                              void* d_out, int out_size)
{
    const float* x    = (const float*)d_in[0];
    const float* grid = (const float*)d_in[1];
    if (in_sizes[0] != BATCH * CH * HW) {     // pick by size, defensively
        const float* t = x; x = grid; grid = t;
    }

    zero_kernel<<<ZBLOCKS, ZTHREADS>>>();
    scatter_kernel<<<(NPTS / 2) / 256, 256>>>((const float2*)x, (const float4*)grid);
    transpose_kernel<<<(BATCH * HH) / 4, 256>>>((float*)d_out);
}